// round 7
// baseline (speedup 1.0000x reference)
#include <cuda_runtime.h>
#include <cstdint>

// SiLU(x) = x * sigmoid(x), elementwise, n = 134217728 fp32.
// TMA bulk-burst pipeline: cp.async.bulk 1D loads (8KB) -> smem ring (3 stages),
// compute in smem, cp.async.bulk stores (8KB bursts) with double-buffered output.
// Goal: large same-direction DRAM bursts to cut read/write turnaround vs the
// 86%-DRAM LDG/STG plateau.

#define STAGES        3
#define OUTBUFS       2
#define STAGE_FLOATS  2048            // 8 KB per stage
#define STAGE_BYTES   (STAGE_FLOATS * 4)
#define THREADS       256
#define TILES_PER_CTA 8

__device__ __forceinline__ float silu1(float x) {
    float s = 1.0f / (1.0f + __expf(-x));
    return x * s;
}

__device__ __forceinline__ float4 silu4(float4 v) {
    float4 r;
    r.x = silu1(v.x); r.y = silu1(v.y);
    r.z = silu1(v.z); r.w = silu1(v.w);
    return r;
}

__device__ __forceinline__ uint32_t smem_u32(const void* p) {
    return (uint32_t)__cvta_generic_to_shared(p);
}

__device__ __forceinline__ void mbar_init(uint32_t mbar, uint32_t count) {
    asm volatile("mbarrier.init.shared.b64 [%0], %1;" :: "r"(mbar), "r"(count) : "memory");
}

__device__ __forceinline__ void mbar_expect_tx(uint32_t mbar, uint32_t bytes) {
    asm volatile("mbarrier.arrive.expect_tx.shared.b64 _, [%0], %1;"
                 :: "r"(mbar), "r"(bytes) : "memory");
}

__device__ __forceinline__ void mbar_wait(uint32_t mbar, uint32_t parity) {
    uint32_t done;
    asm volatile(
        "{\n\t.reg .pred p;\n\t"
        "mbarrier.try_wait.parity.acquire.cta.shared::cta.b64 p, [%1], %2;\n\t"
        "selp.b32 %0, 1, 0, p;\n\t}"
        : "=r"(done) : "r"(mbar), "r"(parity) : "memory");
    if (!done) {
        asm volatile(
            "{\n\t.reg .pred P1;\n\t"
            "W_%=:\n\t"
            "mbarrier.try_wait.parity.acquire.cta.shared::cta.b64 P1, [%0], %1, 0x989680;\n\t"
            "@P1 bra.uni D_%=;\n\t"
            "bra.uni W_%=;\n\t"
            "D_%=:\n\t}"
            :: "r"(mbar), "r"(parity) : "memory");
    }
}

__device__ __forceinline__ void bulk_load(uint32_t dst_smem, const void* src_gmem,
                                          uint32_t bytes, uint32_t mbar) {
    asm volatile(
        "cp.async.bulk.shared::cta.global.mbarrier::complete_tx::bytes [%0], [%1], %2, [%3];"
        :: "r"(dst_smem), "l"(src_gmem), "r"(bytes), "r"(mbar) : "memory");
}

__device__ __forceinline__ void bulk_store(void* dst_gmem, uint32_t src_smem,
                                           uint32_t bytes) {
    asm volatile(
        "cp.async.bulk.global.shared::cta.bulk_group [%0], [%1], %2;"
        :: "l"(dst_gmem), "r"(src_smem), "r"(bytes) : "memory");
}

__global__ void __launch_bounds__(THREADS) silu_tma_pipeline_kernel(
    const float* __restrict__ in, float* __restrict__ out)
{
    __shared__ __align__(16) float sin[STAGES][STAGE_FLOATS];
    __shared__ __align__(16) float sout[OUTBUFS][STAGE_FLOATS];
    __shared__ __align__(8)  uint64_t mbar_storage[STAGES];

    const int tid = threadIdx.x;
    const long long tile0 = (long long)blockIdx.x * TILES_PER_CTA;

    uint32_t mb[STAGES];
    #pragma unroll
    for (int s = 0; s < STAGES; s++) mb[s] = smem_u32(&mbar_storage[s]);

    if (tid == 0) {
        #pragma unroll
        for (int s = 0; s < STAGES; s++) mbar_init(mb[s], 1);
    }
    __syncthreads();

    // Prologue: prefetch first STAGES tiles.
    if (tid == 0) {
        #pragma unroll
        for (int s = 0; s < STAGES && s < TILES_PER_CTA; s++) {
            mbar_expect_tx(mb[s], STAGE_BYTES);
            bulk_load(smem_u32(sin[s]), in + (tile0 + s) * STAGE_FLOATS,
                      STAGE_BYTES, mb[s]);
        }
    }

    for (int t = 0; t < TILES_PER_CTA; t++) {
        const int s  = t % STAGES;
        const int ob = t % OUTBUFS;
        const uint32_t parity = (t / STAGES) & 1;

        // All threads wait for the load of this stage.
        mbar_wait(mb[s], parity);

        // Ensure the output buffer's previous bulk store has drained.
        if (tid == 0) {
            asm volatile("cp.async.bulk.wait_group %0;" :: "n"(OUTBUFS - 1) : "memory");
        }
        __syncthreads();

        // Compute: 2048 floats, 2 float4 per thread.
        const float4* si = (const float4*)sin[s];
        float4*       so = (float4*)sout[ob];
        so[tid]           = silu4(si[tid]);
        so[tid + THREADS] = silu4(si[tid + THREADS]);

        __syncthreads();

        if (tid == 0) {
            // Make generic-proxy smem writes visible to async proxy, then store.
            asm volatile("fence.proxy.async.shared::cta;" ::: "memory");
            bulk_store(out + (tile0 + t) * STAGE_FLOATS, smem_u32(sout[ob]),
                       STAGE_BYTES);
            asm volatile("cp.async.bulk.commit_group;" ::: "memory");

            // Refill this input stage with the tile STAGES ahead.
            const int tn = t + STAGES;
            if (tn < TILES_PER_CTA) {
                mbar_expect_tx(mb[s], STAGE_BYTES);
                bulk_load(smem_u32(sin[s]), in + (tile0 + tn) * STAGE_FLOATS,
                          STAGE_BYTES, mb[s]);
            }
        }
    }

    // Drain all outstanding bulk stores before CTA exit.
    if (tid == 0) {
        asm volatile("cp.async.bulk.wait_group %0;" :: "n"(0) : "memory");
    }
}

// ---------------- fallback paths (generic shapes) ----------------

__global__ void __launch_bounds__(512) silu_b512_full_kernel(
    const float4* __restrict__ in, float4* __restrict__ out)
{
    unsigned base = blockIdx.x * 2048u + threadIdx.x;
    float4 v0 = __ldcs(in + base);
    float4 v1 = __ldcs(in + base + 512);
    float4 v2 = __ldcs(in + base + 1024);
    float4 v3 = __ldcs(in + base + 1536);
    __stcs(out + base,        silu4(v0));
    __stcs(out + base + 512,  silu4(v1));
    __stcs(out + base + 1024, silu4(v2));
    __stcs(out + base + 1536, silu4(v3));
}

__global__ void __launch_bounds__(256) silu_guarded_kernel(
    const float4* __restrict__ in, float4* __restrict__ out, int n4)
{
    int base = blockIdx.x * 1024 + threadIdx.x;
    #pragma unroll
    for (int k = 0; k < 4; k++) {
        int i = base + k * 256;
        if (i < n4) __stcs(out + i, silu4(__ldcs(in + i)));
    }
}

__global__ void silu_tail_kernel(const float* __restrict__ in,
                                 float* __restrict__ out, int start, int n)
{
    int i = start + blockIdx.x * blockDim.x + threadIdx.x;
    if (i < n) out[i] = silu1(in[i]);
}

extern "C" void kernel_launch(void* const* d_in, const int* in_sizes, int n_in,
                              void* d_out, int out_size)
{
    const float* x = (const float*)d_in[0];
    float* y = (float*)d_out;
    int n = in_sizes[0];

    const int chunk = STAGE_FLOATS * TILES_PER_CTA;   // 16384 floats per CTA
    if (n > 0 && (n % chunk) == 0) {
        int grid = n / chunk;                         // 8192 CTAs for this shape
        silu_tma_pipeline_kernel<<<grid, THREADS>>>(x, y);
        return;
    }

    int n4 = n / 4;
    if (n4 > 0) {
        if ((n4 & 2047) == 0) {
            silu_b512_full_kernel<<<n4 / 2048, 512>>>(
                (const float4*)x, (float4*)y);
        } else {
            silu_guarded_kernel<<<(n4 + 1023) / 1024, 256>>>(
                (const float4*)x, (float4*)y, n4);
        }
    }
    int rem = n - n4 * 4;
    if (rem > 0) {
        silu_tail_kernel<<<1, 256>>>(x, y, n4 * 4, n);
    }
}

// round 8
// speedup vs baseline: 1.0210x; 1.0210x over previous
#include <cuda_runtime.h>
#include <cuda_bf16.h>

// SiLU(x) = x * sigmoid(x), elementwise, n = 134217728 fp32.
// HBM-bound stream at the ~86%-of-spec mixed R/W ceiling (~6.8 TB/s measured).
// 1024-thread blocks, 4 front-batched LDG.128 per thread (MLP=4),
// tile = 4096 float4s, grid = 8192, non-temporal hints, no guards on fast path.

__device__ __forceinline__ float silu1(float x) {
    float s = 1.0f / (1.0f + __expf(-x));
    return x * s;
}

__device__ __forceinline__ float4 silu4(float4 v) {
    float4 r;
    r.x = silu1(v.x);
    r.y = silu1(v.y);
    r.z = silu1(v.z);
    r.w = silu1(v.w);
    return r;
}

// Full-tile kernel: every block owns exactly 4096 float4s, no guards.
__global__ void __launch_bounds__(1024) silu_b1024_full_kernel(
    const float4* __restrict__ in, float4* __restrict__ out)
{
    unsigned base = blockIdx.x * 4096u + threadIdx.x;
    float4 v0 = __ldcs(in + base);
    float4 v1 = __ldcs(in + base + 1024);
    float4 v2 = __ldcs(in + base + 2048);
    float4 v3 = __ldcs(in + base + 3072);
    __stcs(out + base,        silu4(v0));
    __stcs(out + base + 1024, silu4(v1));
    __stcs(out + base + 2048, silu4(v2));
    __stcs(out + base + 3072, silu4(v3));
}

// R6 winner kept as secondary fast path (n4 % 2048 == 0 but not % 4096).
__global__ void __launch_bounds__(512) silu_b512_full_kernel(
    const float4* __restrict__ in, float4* __restrict__ out)
{
    unsigned base = blockIdx.x * 2048u + threadIdx.x;
    float4 v0 = __ldcs(in + base);
    float4 v1 = __ldcs(in + base + 512);
    float4 v2 = __ldcs(in + base + 1024);
    float4 v3 = __ldcs(in + base + 1536);
    __stcs(out + base,        silu4(v0));
    __stcs(out + base + 512,  silu4(v1));
    __stcs(out + base + 1024, silu4(v2));
    __stcs(out + base + 1536, silu4(v3));
}

// Generic guarded kernel (fallback for shapes not divisible by tile).
__global__ void __launch_bounds__(256) silu_guarded_kernel(
    const float4* __restrict__ in, float4* __restrict__ out, int n4)
{
    int base = blockIdx.x * 1024 + threadIdx.x;
    #pragma unroll
    for (int k = 0; k < 4; k++) {
        int i = base + k * 256;
        if (i < n4) __stcs(out + i, silu4(__ldcs(in + i)));
    }
}

// Tail for n not divisible by 4 (not hit for this shape).
__global__ void silu_tail_kernel(const float* __restrict__ in,
                                 float* __restrict__ out, int start, int n)
{
    int i = start + blockIdx.x * blockDim.x + threadIdx.x;
    if (i < n) out[i] = silu1(in[i]);
}

extern "C" void kernel_launch(void* const* d_in, const int* in_sizes, int n_in,
                              void* d_out, int out_size)
{
    const float* x = (const float*)d_in[0];
    float* y = (float*)d_out;
    int n = in_sizes[0];

    int n4 = n / 4;
    if (n4 > 0) {
        if ((n4 & 4095) == 0) {
            silu_b1024_full_kernel<<<n4 / 4096, 1024>>>(
                (const float4*)x, (float4*)y);
        } else if ((n4 & 2047) == 0) {
            silu_b512_full_kernel<<<n4 / 2048, 512>>>(
                (const float4*)x, (float4*)y);
        } else {
            silu_guarded_kernel<<<(n4 + 1023) / 1024, 256>>>(
                (const float4*)x, (float4*)y, n4);
        }
    }
    int rem = n - n4 * 4;
    if (rem > 0) {
        silu_tail_kernel<<<1, 256>>>(x, y, n4 * 4, n);
    }
}